// round 2
// baseline (speedup 1.0000x reference)
#include <cuda_runtime.h>
#include <cuda_bf16.h>

// Scratch (alloc-free rule: __device__ globals). N = 100000 <= MAXN.
#define MAXN (1 << 17)
__device__ float g_deg[MAXN];
__device__ float g_dinv[MAXN];
__device__ float g_S[MAXN];
__device__ float g_t[MAXN];

// ---------------------------------------------------------------------------
// Node kernels (tiny, O(N))
// ---------------------------------------------------------------------------

// deg starts at 1.0 (self loop), S at 0.
__global__ void init_kernel(int n) {
    int i = blockIdx.x * blockDim.x + threadIdx.x;
    if (i < n) {
        g_deg[i] = 1.0f;
        g_S[i]   = 0.0f;
    }
}

__global__ void dinv_kernel(int n) {
    int i = blockIdx.x * blockDim.x + threadIdx.x;
    if (i < n) {
        // deg >= 1 always (self loops) — matches reference where()/max() path.
        g_dinv[i] = 1.0f / sqrtf(g_deg[i]);
    }
}

// Per-node tiny MLP: s = S[i] + dinv^2 * x[i] (layer-1 self-loop term),
// t[i] = sum_k relu(W1[k]*s + b1[k]) * W2[k].
// Seeds out[i] with the layer-2 self-loop + bias; edge pass adds the rest.
__global__ void t_kernel(const float* __restrict__ x,
                         const float* __restrict__ W1,
                         const float* __restrict__ b1,
                         const float* __restrict__ W2,
                         const float* __restrict__ b2,
                         float* __restrict__ out,
                         int n, int H) {
    int i = blockIdx.x * blockDim.x + threadIdx.x;
    if (i < n) {
        float di = g_dinv[i];
        float s  = g_S[i] + di * di * __ldg(&x[i]);
        float acc = 0.0f;
        #pragma unroll 16
        for (int k = 0; k < H; k++) {
            float h = fmaf(__ldg(&W1[k]), s, __ldg(&b1[k]));
            h = fmaxf(h, 0.0f);
            acc = fmaf(h, __ldg(&W2[k]), acc);
        }
        g_t[i] = acc;
        out[i] = di * di * acc + __ldg(&b2[0]);
    }
}

// ---------------------------------------------------------------------------
// Edge kernels (int32 indices; 4 edges/thread via 16B int4 loads)
// ---------------------------------------------------------------------------

__global__ void deg_kernel(const int* __restrict__ col, int E) {
    int i = blockIdx.x * blockDim.x + threadIdx.x;
    int e = i * 4;
    if (e + 3 < E) {
        int4 c = *reinterpret_cast<const int4*>(col + e);
        atomicAdd(&g_deg[c.x], 1.0f);
        atomicAdd(&g_deg[c.y], 1.0f);
        atomicAdd(&g_deg[c.z], 1.0f);
        atomicAdd(&g_deg[c.w], 1.0f);
    } else {
        for (; e < E; e++) atomicAdd(&g_deg[col[e]], 1.0f);
    }
}

// S[col] += dinv[row]*dinv[col]*x[row]
__global__ void s_kernel(const int* __restrict__ row,
                         const int* __restrict__ col,
                         const float* __restrict__ x, int E) {
    int i = blockIdx.x * blockDim.x + threadIdx.x;
    int e = i * 4;
    if (e + 3 < E) {
        int4 r = *reinterpret_cast<const int4*>(row + e);
        int4 c = *reinterpret_cast<const int4*>(col + e);
        float v0 = g_dinv[r.x] * g_dinv[c.x] * __ldg(&x[r.x]);
        float v1 = g_dinv[r.y] * g_dinv[c.y] * __ldg(&x[r.y]);
        float v2 = g_dinv[r.z] * g_dinv[c.z] * __ldg(&x[r.z]);
        float v3 = g_dinv[r.w] * g_dinv[c.w] * __ldg(&x[r.w]);
        atomicAdd(&g_S[c.x], v0);
        atomicAdd(&g_S[c.y], v1);
        atomicAdd(&g_S[c.z], v2);
        atomicAdd(&g_S[c.w], v3);
    } else {
        for (; e < E; e++) {
            int r0 = row[e], c0 = col[e];
            atomicAdd(&g_S[c0], g_dinv[r0] * g_dinv[c0] * __ldg(&x[r0]));
        }
    }
}

// out[col] += dinv[row]*dinv[col]*t[row]
__global__ void out_kernel(const int* __restrict__ row,
                           const int* __restrict__ col,
                           float* __restrict__ out, int E) {
    int i = blockIdx.x * blockDim.x + threadIdx.x;
    int e = i * 4;
    if (e + 3 < E) {
        int4 r = *reinterpret_cast<const int4*>(row + e);
        int4 c = *reinterpret_cast<const int4*>(col + e);
        float v0 = g_dinv[r.x] * g_dinv[c.x] * g_t[r.x];
        float v1 = g_dinv[r.y] * g_dinv[c.y] * g_t[r.y];
        float v2 = g_dinv[r.z] * g_dinv[c.z] * g_t[r.z];
        float v3 = g_dinv[r.w] * g_dinv[c.w] * g_t[r.w];
        atomicAdd(&out[c.x], v0);
        atomicAdd(&out[c.y], v1);
        atomicAdd(&out[c.z], v2);
        atomicAdd(&out[c.w], v3);
    } else {
        for (; e < E; e++) {
            int r0 = row[e], c0 = col[e];
            atomicAdd(&out[c0], g_dinv[r0] * g_dinv[c0] * g_t[r0]);
        }
    }
}

// ---------------------------------------------------------------------------
// Launch
// ---------------------------------------------------------------------------

extern "C" void kernel_launch(void* const* d_in, const int* in_sizes, int n_in,
                              void* d_out, int out_size) {
    const float* x    = (const float*)d_in[0];
    const int*   eidx = (const int*)d_in[1];    // [2, E] int32 (JAX default x64 off)
    const float* W1   = (const float*)d_in[2];
    const float* b1   = (const float*)d_in[3];
    const float* W2   = (const float*)d_in[4];
    const float* b2   = (const float*)d_in[5];
    float*       out  = (float*)d_out;

    int N = in_sizes[0];          // x is [N,1]
    int E = in_sizes[1] / 2;      // edge_index is [2,E]
    int H = in_sizes[3];          // hidden dim = len(b1) = 16

    const int* row = eidx;
    const int* col = eidx + E;

    const int TB = 256;
    int nodeBlocks = (N + TB - 1) / TB;
    int edgeThreads = (E + 3) / 4;
    int edgeBlocks = (edgeThreads + TB - 1) / TB;

    init_kernel<<<nodeBlocks, TB>>>(N);
    deg_kernel<<<edgeBlocks, TB>>>(col, E);
    dinv_kernel<<<nodeBlocks, TB>>>(N);
    s_kernel<<<edgeBlocks, TB>>>(row, col, x, E);
    t_kernel<<<nodeBlocks, TB>>>(x, W1, b1, W2, b2, out, N, H);
    out_kernel<<<edgeBlocks, TB>>>(row, col, out, E);
}

// round 3
// speedup vs baseline: 1.3389x; 1.3389x over previous
#include <cuda_runtime.h>
#include <cuda_bf16.h>

// Scratch (alloc-free rule: __device__ globals). N = 100000 <= MAXN.
#define MAXN (1 << 17)
__device__ float g_deg[MAXN];
__device__ float g_dinv[MAXN];
__device__ float g_a[MAXN];    // dinv[i]*x[i]   (layer-1 source values)
__device__ float g_S[MAXN];    // unnormalized layer-1 aggregate
__device__ float g_u[MAXN];    // dinv[i]*t[i]   (layer-2 source values)
__device__ float g_acc[MAXN];  // unnormalized layer-2 aggregate

// ---------------------------------------------------------------------------
// Node kernels (tiny, O(N))
// ---------------------------------------------------------------------------

__global__ void init_kernel(int n) {
    int i = blockIdx.x * blockDim.x + threadIdx.x;
    if (i < n) {
        g_deg[i] = 1.0f;   // self loop
        g_S[i]   = 0.0f;
        g_acc[i] = 0.0f;
    }
}

// dinv[i] = 1/sqrt(deg[i]); a[i] = dinv[i]*x[i]
__global__ void prep_kernel(const float* __restrict__ x, int n) {
    int i = blockIdx.x * blockDim.x + threadIdx.x;
    if (i < n) {
        float di = 1.0f / sqrtf(g_deg[i]);   // deg >= 1 always (self loops)
        g_dinv[i] = di;
        g_a[i]    = di * __ldg(&x[i]);
    }
}

// s = dinv[i]*(S'[i] + a[i])  (the +a[i] is the self-loop edge)
// t[i] = sum_k relu(W1[k]*s + b1[k]) * W2[k];  u[i] = dinv[i]*t[i]
__global__ void t_kernel(const float* __restrict__ W1,
                         const float* __restrict__ b1,
                         const float* __restrict__ W2,
                         int n, int H) {
    int i = blockIdx.x * blockDim.x + threadIdx.x;
    if (i < n) {
        float di = g_dinv[i];
        float s  = di * (g_S[i] + g_a[i]);
        float acc = 0.0f;
        #pragma unroll 16
        for (int k = 0; k < H; k++) {
            float h = fmaf(__ldg(&W1[k]), s, __ldg(&b1[k]));
            h = fmaxf(h, 0.0f);
            acc = fmaf(h, __ldg(&W2[k]), acc);
        }
        g_u[i] = di * acc;
    }
}

// out[i] = dinv[i]*(acc[i] + u[i]) + b2   (the +u[i] is the self-loop edge)
__global__ void final_kernel(const float* __restrict__ b2,
                             float* __restrict__ out, int n) {
    int i = blockIdx.x * blockDim.x + threadIdx.x;
    if (i < n) {
        out[i] = g_dinv[i] * (g_acc[i] + g_u[i]) + __ldg(&b2[0]);
    }
}

// ---------------------------------------------------------------------------
// Edge kernels (int32 indices; 8 edges/thread via 2x int4 loads)
// Each edge now costs exactly 1 scattered gather + 1 scattered atomic (or
// just 1 atomic for deg) on the L2-resident node arrays.
// ---------------------------------------------------------------------------

__global__ void deg_kernel(const int* __restrict__ col, int E) {
    int i = blockIdx.x * blockDim.x + threadIdx.x;
    int e = i * 8;
    if (e + 7 < E) {
        int4 c0 = *reinterpret_cast<const int4*>(col + e);
        int4 c1 = *reinterpret_cast<const int4*>(col + e + 4);
        atomicAdd(&g_deg[c0.x], 1.0f);
        atomicAdd(&g_deg[c0.y], 1.0f);
        atomicAdd(&g_deg[c0.z], 1.0f);
        atomicAdd(&g_deg[c0.w], 1.0f);
        atomicAdd(&g_deg[c1.x], 1.0f);
        atomicAdd(&g_deg[c1.y], 1.0f);
        atomicAdd(&g_deg[c1.z], 1.0f);
        atomicAdd(&g_deg[c1.w], 1.0f);
    } else {
        for (; e < E; e++) atomicAdd(&g_deg[col[e]], 1.0f);
    }
}

// S'[col] += a[row]
__global__ void s_kernel(const int* __restrict__ row,
                         const int* __restrict__ col, int E) {
    int i = blockIdx.x * blockDim.x + threadIdx.x;
    int e = i * 8;
    if (e + 7 < E) {
        int4 r0 = *reinterpret_cast<const int4*>(row + e);
        int4 r1 = *reinterpret_cast<const int4*>(row + e + 4);
        int4 c0 = *reinterpret_cast<const int4*>(col + e);
        int4 c1 = *reinterpret_cast<const int4*>(col + e + 4);
        float v0 = g_a[r0.x], v1 = g_a[r0.y], v2 = g_a[r0.z], v3 = g_a[r0.w];
        float v4 = g_a[r1.x], v5 = g_a[r1.y], v6 = g_a[r1.z], v7 = g_a[r1.w];
        atomicAdd(&g_S[c0.x], v0);
        atomicAdd(&g_S[c0.y], v1);
        atomicAdd(&g_S[c0.z], v2);
        atomicAdd(&g_S[c0.w], v3);
        atomicAdd(&g_S[c1.x], v4);
        atomicAdd(&g_S[c1.y], v5);
        atomicAdd(&g_S[c1.z], v6);
        atomicAdd(&g_S[c1.w], v7);
    } else {
        for (; e < E; e++) atomicAdd(&g_S[col[e]], g_a[row[e]]);
    }
}

// acc[col] += u[row]
__global__ void out_kernel(const int* __restrict__ row,
                           const int* __restrict__ col, int E) {
    int i = blockIdx.x * blockDim.x + threadIdx.x;
    int e = i * 8;
    if (e + 7 < E) {
        int4 r0 = *reinterpret_cast<const int4*>(row + e);
        int4 r1 = *reinterpret_cast<const int4*>(row + e + 4);
        int4 c0 = *reinterpret_cast<const int4*>(col + e);
        int4 c1 = *reinterpret_cast<const int4*>(col + e + 4);
        float v0 = g_u[r0.x], v1 = g_u[r0.y], v2 = g_u[r0.z], v3 = g_u[r0.w];
        float v4 = g_u[r1.x], v5 = g_u[r1.y], v6 = g_u[r1.z], v7 = g_u[r1.w];
        atomicAdd(&g_acc[c0.x], v0);
        atomicAdd(&g_acc[c0.y], v1);
        atomicAdd(&g_acc[c0.z], v2);
        atomicAdd(&g_acc[c0.w], v3);
        atomicAdd(&g_acc[c1.x], v4);
        atomicAdd(&g_acc[c1.y], v5);
        atomicAdd(&g_acc[c1.z], v6);
        atomicAdd(&g_acc[c1.w], v7);
    } else {
        for (; e < E; e++) atomicAdd(&g_acc[col[e]], g_u[row[e]]);
    }
}

// ---------------------------------------------------------------------------
// Launch
// ---------------------------------------------------------------------------

extern "C" void kernel_launch(void* const* d_in, const int* in_sizes, int n_in,
                              void* d_out, int out_size) {
    const float* x    = (const float*)d_in[0];
    const int*   eidx = (const int*)d_in[1];    // [2, E] int32
    const float* W1   = (const float*)d_in[2];
    const float* b1   = (const float*)d_in[3];
    const float* W2   = (const float*)d_in[4];
    const float* b2   = (const float*)d_in[5];
    float*       out  = (float*)d_out;

    int N = in_sizes[0];
    int E = in_sizes[1] / 2;
    int H = in_sizes[3];

    const int* row = eidx;
    const int* col = eidx + E;

    const int TB = 256;
    int nodeBlocks = (N + TB - 1) / TB;
    int edgeThreads = (E + 7) / 8;
    int edgeBlocks = (edgeThreads + TB - 1) / TB;

    init_kernel<<<nodeBlocks, TB>>>(N);
    deg_kernel<<<edgeBlocks, TB>>>(col, E);
    prep_kernel<<<nodeBlocks, TB>>>(x, N);
    s_kernel<<<edgeBlocks, TB>>>(row, col, E);
    t_kernel<<<nodeBlocks, TB>>>(W1, b1, W2, N, H);
    out_kernel<<<edgeBlocks, TB>>>(row, col, E);
    final_kernel<<<nodeBlocks, TB>>>(b2, out, N);
}